// round 1
// baseline (speedup 1.0000x reference)
#include <cuda_runtime.h>

// DistanceTransformMap: exact 2-pass squared EDT + sqrt.
// B=4, C=1, H=W=384. mask in {0,1} float32 -> out float32 [B,1,H,W].
//
// Pass 1 (along W): f[x] = mask>0.5 ? LARGE : 0; out1[x] = min_j f[j]+(x-j)^2.
//   Written TRANSPOSED into g_mid[b][x][y] so pass 2 reads coalesced rows.
// Pass 2 (along H): out[y] = sqrt( min_j mid[j]+(y-j)^2 ).
//
// Inner step uses g[j] = f[j] + j^2 staged in shared:
//   f[j]+(i-j)^2 = i^2 + (g[j] - 2i*j)
// Fully-unrolled j-loop makes (float)j an FFMA immediate (rt_SMSP=1 on sm_103a),
// FMNMX runs on the alu pipe in parallel. All intermediates are exact integers
// < 2^24 in fp32, so the result is bit-exact vs the reference.

constexpr int Bn = 4;
constexpr int Hn = 384;
constexpr int Wn = 384;
constexpr float LARGE = 2.0f * (float)(Hn * Hn + Wn * Wn);  // 589824

__device__ float g_mid[Bn * Wn * Hn];  // transposed intermediate [b][x][y]

__global__ __launch_bounds__(Wn) void edt_pass1(const float* __restrict__ mask) {
    __shared__ __align__(16) float sh_g[Wn];
    const int r = blockIdx.x;               // r = b*Hn + y
    const int b = r / Hn;
    const int y = r - b * Hn;
    const int x = threadIdx.x;
    const float xf = (float)x;

    const float m = mask[r * Wn + x];
    sh_g[x] = (m > 0.5f ? LARGE : 0.0f) + xf * xf;   // g[j] = f[j] + j^2
    __syncthreads();

    const float m2i = -2.0f * xf;
    float a0 = 3.0e38f, a1 = 3.0e38f, a2 = 3.0e38f, a3 = 3.0e38f;
#pragma unroll
    for (int j = 0; j < Wn; j += 4) {
        const float4 g = *reinterpret_cast<const float4*>(&sh_g[j]);
        a0 = fminf(a0, fmaf(m2i, (float)(j + 0), g.x));
        a1 = fminf(a1, fmaf(m2i, (float)(j + 1), g.y));
        a2 = fminf(a2, fmaf(m2i, (float)(j + 2), g.z));
        a3 = fminf(a3, fmaf(m2i, (float)(j + 3), g.w));
    }
    const float minv = fminf(fminf(a0, a1), fminf(a2, a3));
    // transposed scatter write: [b][x][y]
    g_mid[(b * Wn + x) * Hn + y] = xf * xf + minv;
}

__global__ __launch_bounds__(Hn) void edt_pass2(float* __restrict__ out) {
    __shared__ __align__(16) float sh_g[Hn];
    const int c = blockIdx.x;               // c = b*Wn + x
    const int b = c / Wn;
    const int x = c - b * Wn;
    const int y = threadIdx.x;
    const float yf = (float)y;

    sh_g[y] = g_mid[c * Hn + y] + yf * yf;  // coalesced row read
    __syncthreads();

    const float m2i = -2.0f * yf;
    float a0 = 3.0e38f, a1 = 3.0e38f, a2 = 3.0e38f, a3 = 3.0e38f;
#pragma unroll
    for (int j = 0; j < Hn; j += 4) {
        const float4 g = *reinterpret_cast<const float4*>(&sh_g[j]);
        a0 = fminf(a0, fmaf(m2i, (float)(j + 0), g.x));
        a1 = fminf(a1, fmaf(m2i, (float)(j + 1), g.y));
        a2 = fminf(a2, fmaf(m2i, (float)(j + 2), g.z));
        a3 = fminf(a3, fmaf(m2i, (float)(j + 3), g.w));
    }
    const float minv = fminf(fminf(a0, a1), fminf(a2, a3));
    out[(b * Hn + y) * Wn + x] = sqrtf(yf * yf + minv);
}

extern "C" void kernel_launch(void* const* d_in, const int* in_sizes, int n_in,
                              void* d_out, int out_size) {
    const float* mask = (const float*)d_in[0];
    float* out = (float*)d_out;
    (void)in_sizes; (void)n_in; (void)out_size;

    edt_pass1<<<Bn * Hn, Wn>>>(mask);
    edt_pass2<<<Bn * Wn, Hn>>>(out);
}

// round 2
// speedup vs baseline: 2.8035x; 2.8035x over previous
#include <cuda_runtime.h>

// DistanceTransformMap: exact 2-pass EDT + sqrt, expanding-window search.
// B=4, C=1, H=W=384. mask in {0,1} float32 -> out float32 [B,1,H,W].
//
// Exactness of early exit: all g[j] >= 0, so g[j] + d^2 >= d^2. Once
// d^2 >= best, no candidate at distance >= d can improve best (d^2 is
// monotone and the condition is re-tested every step as best shrinks).
// Hence scanning d = 1,2,... outward from i and stopping at d^2 >= best
// yields exactly min_j g[j] + (i-j)^2. All values are exact integers
// < 2^24 in fp32 -> bit-exact vs the reference brute force.
//
// Pass 1: g = mask>0.5 ? LARGE : 0 per row (LARGE = 2*(H^2+W^2) = 589824
// > 383^2, so foreground candidates never beat a real zero; an
// all-foreground row correctly yields LARGE, matching the reference).
// Pass 2: column EDT on the pass-1 field, in 8-column strips so global
// traffic stays coalesced and the search runs in shared memory.

constexpr int Bn = 4;
constexpr int Hn = 384;
constexpr int Wn = 384;
constexpr int COLS = 8;                      // columns per pass-2 block
constexpr float LARGE = 2.0f * (float)(Hn * Hn + Wn * Wn);  // 589824

__device__ float g_mid[Bn * Hn * Wn];        // natural layout [b][y][x]

__global__ __launch_bounds__(Wn) void edt_pass1(const float* __restrict__ mask) {
    __shared__ float sh[Wn];
    const int r = blockIdx.x;                // r = b*Hn + y
    const int i = threadIdx.x;

    const float m = mask[r * Wn + i];
    sh[i] = (m > 0.5f) ? LARGE : 0.0f;       // f[j]
    __syncthreads();

    float best = sh[i];                      // d = 0 candidate
    float df = 1.0f;
    int d = 1;
    while (df * df < best && d < Wn) {
        const float dd = df * df;
        const int jl = i - d, jr = i + d;
        if (jl >= 0) best = fminf(best, sh[jl] + dd);
        if (jr < Wn) best = fminf(best, sh[jr] + dd);
        df += 1.0f;
        ++d;
    }
    g_mid[r * Wn + i] = best;                // coalesced row write
}

__global__ __launch_bounds__(32 * COLS) void edt_pass2(float* __restrict__ out) {
    __shared__ float sh[Hn][COLS + 1];       // [y][c], stride 9 -> conflict-free
    const int blk = blockIdx.x;              // b*(Wn/COLS) + strip
    const int b = blk / (Wn / COLS);
    const int x0 = (blk - b * (Wn / COLS)) * COLS;
    const int t = threadIdx.x;
    const int nthr = 32 * COLS;

    // Coalesced tile load: 8 consecutive floats per y = full 32B sectors.
    const float* __restrict__ src = g_mid + (size_t)b * Hn * Wn + x0;
    for (int k = t; k < Hn * COLS; k += nthr) {
        const int y = k >> 3, c = k & 7;
        sh[y][c] = src[y * Wn + c];
    }
    __syncthreads();

    const int w = t >> 5;                    // warp <-> column
    const int lane = t & 31;

    float res[Hn / 32];
#pragma unroll
    for (int mo = 0; mo < Hn / 32; ++mo) {
        const int y = lane + 32 * mo;
        float best = sh[y][w];
        float df = 1.0f;
        int d = 1;
        while (df * df < best && d < Hn) {
            const float dd = df * df;
            const int yl = y - d, yr = y + d;
            if (yl >= 0) best = fminf(best, sh[yl][w] + dd);
            if (yr < Hn) best = fminf(best, sh[yr][w] + dd);
            df += 1.0f;
            ++d;
        }
        res[mo] = sqrtf(best);
    }
    __syncthreads();                         // all reads of sh done

#pragma unroll
    for (int mo = 0; mo < Hn / 32; ++mo)
        sh[lane + 32 * mo][w] = res[mo];
    __syncthreads();

    // Coalesced tile store, mirroring the load.
    float* __restrict__ dst = out + (size_t)b * Hn * Wn + x0;
    for (int k = t; k < Hn * COLS; k += nthr) {
        const int y = k >> 3, c = k & 7;
        dst[y * Wn + c] = sh[y][c];
    }
}

extern "C" void kernel_launch(void* const* d_in, const int* in_sizes, int n_in,
                              void* d_out, int out_size) {
    const float* mask = (const float*)d_in[0];
    float* out = (float*)d_out;
    (void)in_sizes; (void)n_in; (void)out_size;

    edt_pass1<<<Bn * Hn, Wn>>>(mask);
    edt_pass2<<<Bn * (Wn / COLS), 32 * COLS>>>(out);
}